// round 1
// baseline (speedup 1.0000x reference)
#include <cuda_runtime.h>
#include <cstdint>

#define N_NODES  50000
#define N_EDGES  800000
#define IN_FEAT  256
#define OUT_FEAT 128
#define P_EDGE   0.2f
#define P_NODE   0.1f
#define BN_EPS   1e-5f

// ----------------------------- scratch (no allocs allowed) ------------------
__device__ float g_h[(size_t)N_NODES * OUT_FEAT];
__device__ float g_agg[(size_t)N_NODES * OUT_FEAT];
__device__ float g_deg_src[N_NODES];
__device__ float g_deg_dst[N_NODES];
__device__ float g_sum[OUT_FEAT];
__device__ float g_sumsq[OUT_FEAT];
__device__ float g_scale[OUT_FEAT];
__device__ float g_shift[OUT_FEAT];
__device__ int   g_idx64;   // 1 if src/dst buffers are int64, 0 if int32

__device__ __forceinline__ long long get_idx(const void* p, int e, int is64) {
    return is64 ? ((const long long*)p)[e] : (long long)((const int*)p)[e];
}

// ----------------------------- init + dtype sniff ---------------------------
__global__ void k_init(const float* __restrict__ b, const void* __restrict__ src) {
    int i = blockIdx.x * blockDim.x + threadIdx.x;
    const int total4 = N_NODES * OUT_FEAT / 4;
    if (i < total4) {
        int c = (i & 31) * 4;   // 32 float4 per 128-col row
        ((float4*)g_agg)[i] = make_float4(b[c], b[c + 1], b[c + 2], b[c + 3]);
    }
    if (i < N_NODES) { g_deg_src[i] = 0.f; g_deg_dst[i] = 0.f; }
    if (i < OUT_FEAT) { g_sum[i] = 0.f; g_sumsq[i] = 0.f; }
    if (i == 0) {
        // int64 values < 2^31 have zero high 32-bit words; int32 random
        // indices in [0,50000) make 256 consecutive zero odd-words impossible.
        const unsigned* p = (const unsigned*)src;
        int is64 = 1;
        for (int k = 0; k < 256; k++)
            if (p[2 * k + 1] != 0u) { is64 = 0; break; }
        g_idx64 = is64;
    }
}

// ----------------------------- degrees on dropped graph ---------------------
__global__ void k_deg(const void* __restrict__ src, const void* __restrict__ dst,
                      const float* __restrict__ er) {
    int e = blockIdx.x * blockDim.x + threadIdx.x;
    if (e >= N_EDGES) return;
    if (er[e] >= P_EDGE) {
        int is64 = g_idx64;
        atomicAdd(&g_deg_src[get_idx(src, e, is64)], 1.f);
        atomicAdd(&g_deg_dst[get_idx(dst, e, is64)], 1.f);
    }
}

// ----------------------------- h = features @ W -----------------------------
// BM=64, BN=128, BK=16, 256 threads, thread tile 8x4.
#define BM 64
#define BN 128
#define BK 16
__global__ __launch_bounds__(256)
void k_gemm(const float* __restrict__ A, const float* __restrict__ W) {
    __shared__ float As[BK][BM + 1];
    __shared__ float Bs[BK][BN];

    const int tid  = threadIdx.x;
    const int c    = tid & 31;       // out-col group: cols 4c..4c+3
    const int rg   = tid >> 5;       // row group: rows rg*8..rg*8+7
    const int rowb = blockIdx.x * BM;

    float acc[8][4];
#pragma unroll
    for (int i = 0; i < 8; i++)
#pragma unroll
        for (int j = 0; j < 4; j++) acc[i][j] = 0.f;

    for (int kt = 0; kt < IN_FEAT; kt += BK) {
        // load A tile (64x16), transposed into As[k][m]
        {
            int ar = tid >> 2;
            int kc = (tid & 3) * 4;
            int gr = rowb + ar;
            float4 v = (gr < N_NODES)
                ? ((const float4*)(A + (size_t)gr * IN_FEAT + kt + kc))[0]
                : make_float4(0.f, 0.f, 0.f, 0.f);
            As[kc + 0][ar] = v.x; As[kc + 1][ar] = v.y;
            As[kc + 2][ar] = v.z; As[kc + 3][ar] = v.w;
        }
        // load B tile (16x128): 512 float4, 2 per thread
#pragma unroll
        for (int l = 0; l < 2; l++) {
            int idx = tid + l * 256;
            int kr  = idx >> 5;
            int bc  = (idx & 31) * 4;
            ((float4*)&Bs[kr][bc])[0] =
                ((const float4*)(W + (size_t)(kt + kr) * OUT_FEAT + bc))[0];
        }
        __syncthreads();
#pragma unroll
        for (int k = 0; k < BK; k++) {
            float4 bb = ((float4*)&Bs[k][c * 4])[0];
#pragma unroll
            for (int i = 0; i < 8; i++) {
                float a = As[k][rg * 8 + i];
                acc[i][0] += a * bb.x; acc[i][1] += a * bb.y;
                acc[i][2] += a * bb.z; acc[i][3] += a * bb.w;
            }
        }
        __syncthreads();
    }
#pragma unroll
    for (int i = 0; i < 8; i++) {
        int gr = rowb + rg * 8 + i;
        if (gr < N_NODES)
            ((float4*)(g_h + (size_t)gr * OUT_FEAT + c * 4))[0] =
                make_float4(acc[i][0], acc[i][1], acc[i][2], acc[i][3]);
    }
}

// ----------------------------- edge message passing -------------------------
// one warp per edge: 32 lanes x float4 = 128 features
__global__ __launch_bounds__(256)
void k_msg(const void* __restrict__ src, const void* __restrict__ dst,
           const float* __restrict__ er) {
    int e    = (blockIdx.x * blockDim.x + threadIdx.x) >> 5;
    int lane = threadIdx.x & 31;
    if (e >= N_EDGES) return;
    if (er[e] < P_EDGE) return;

    int is64 = g_idx64;
    long long s = get_idx(src, e, is64);
    long long d = get_idx(dst, e, is64);
    float ds = fmaxf(g_deg_src[s], 1.f);
    float dd = fmaxf(g_deg_dst[d], 1.f);
    float coef = rsqrtf(ds * dd);

    float4 v = ((const float4*)(g_h + (size_t)s * OUT_FEAT))[lane];
    v.x *= coef; v.y *= coef; v.z *= coef; v.w *= coef;

    float* p = g_agg + (size_t)d * OUT_FEAT + lane * 4;
    asm volatile("red.global.add.v4.f32 [%0], {%1,%2,%3,%4};"
                 :: "l"(p), "f"(v.x), "f"(v.y), "f"(v.z), "f"(v.w)
                 : "memory");
}

// ----------------------------- BN statistics --------------------------------
__global__ __launch_bounds__(256)
void k_stats() {
    int tid = threadIdx.x;
    int c   = tid & 127;
    float s = 0.f, sq = 0.f;
    int row    = blockIdx.x * 2 + (tid >> 7);
    int stride = gridDim.x * 2;
    for (int r = row; r < N_NODES; r += stride) {
        float v = g_agg[(size_t)r * OUT_FEAT + c];
        s += v; sq += v * v;
    }
    __shared__ float ss[256], ssq[256];
    ss[tid] = s; ssq[tid] = sq;
    __syncthreads();
    if (tid < 128) {
        atomicAdd(&g_sum[c],   ss[tid]  + ss[tid + 128]);
        atomicAdd(&g_sumsq[c], ssq[tid] + ssq[tid + 128]);
    }
}

__global__ void k_bnparams(const float* __restrict__ gamma,
                           const float* __restrict__ beta) {
    int c = threadIdx.x;
    float inv_n = 1.f / (float)N_NODES;
    float mean = g_sum[c] * inv_n;
    float var  = g_sumsq[c] * inv_n - mean * mean;
    float sc   = rsqrtf(var + BN_EPS) * gamma[c];
    g_scale[c] = sc;
    g_shift[c] = beta[c] - mean * sc;
}

// ----------------------------- finalize: BN + node dropout ------------------
__global__ __launch_bounds__(256)
void k_final(const float* __restrict__ nr, float* __restrict__ out) {
    int i = blockIdx.x * blockDim.x + threadIdx.x;
    const int total4 = N_NODES * OUT_FEAT / 4;
    if (i >= total4) return;
    int c = (i & 31) * 4;
    float4 a = ((const float4*)g_agg)[i];
    float4 r = ((const float4*)nr)[i];
    const float inv_keep = 1.f / (1.f - P_NODE);
    float4 y;
    y.x = (r.x >= P_NODE) ? (a.x * g_scale[c + 0] + g_shift[c + 0]) * inv_keep : 0.f;
    y.y = (r.y >= P_NODE) ? (a.y * g_scale[c + 1] + g_shift[c + 1]) * inv_keep : 0.f;
    y.z = (r.z >= P_NODE) ? (a.z * g_scale[c + 2] + g_shift[c + 2]) * inv_keep : 0.f;
    y.w = (r.w >= P_NODE) ? (a.w * g_scale[c + 3] + g_shift[c + 3]) * inv_keep : 0.f;
    ((float4*)out)[i] = y;
}

// ----------------------------- launch ---------------------------------------
extern "C" void kernel_launch(void* const* d_in, const int* in_sizes, int n_in,
                              void* d_out, int out_size) {
    const float* features = (const float*)d_in[0];
    const float* W        = (const float*)d_in[1];
    const float* b        = (const float*)d_in[2];
    const float* gamma    = (const float*)d_in[3];
    const float* beta     = (const float*)d_in[4];
    const void*  src      = d_in[5];
    const void*  dst      = d_in[6];
    const float* er       = (const float*)d_in[7];
    const float* nr       = (const float*)d_in[8];
    float* out            = (float*)d_out;

    const int total4 = N_NODES * OUT_FEAT / 4;          // 1.6M
    k_init<<<(total4 + 255) / 256, 256>>>(b, src);
    k_deg<<<(N_EDGES + 255) / 256, 256>>>(src, dst, er);
    k_gemm<<<(N_NODES + BM - 1) / BM, 256>>>(features, W);
    {
        long long thr = (long long)N_EDGES * 32;
        k_msg<<<(int)((thr + 255) / 256), 256>>>(src, dst, er);
    }
    k_stats<<<512, 256>>>();
    k_bnparams<<<1, OUT_FEAT>>>(gamma, beta);
    k_final<<<(total4 + 255) / 256, 256>>>(nr, out);
}

// round 2
// speedup vs baseline: 1.0736x; 1.0736x over previous
#include <cuda_runtime.h>
#include <cstdint>

#define N_NODES  50000
#define N_EDGES  800000
#define IN_FEAT  256
#define OUT_FEAT 128
#define P_EDGE   0.2f
#define P_NODE   0.1f
#define BN_EPS   1e-5f

// ----------------------------- scratch (no allocs allowed) ------------------
__device__ float     g_h[(size_t)N_NODES * OUT_FEAT];
__device__ float     g_agg[(size_t)N_NODES * OUT_FEAT];
__device__ int       g_cnt_src[N_NODES];
__device__ int       g_cnt_dst[N_NODES];
__device__ int       g_off[N_NODES + 1];
__device__ int       g_cur[N_NODES];
__device__ long long g_rec[N_EDGES];          // packed {lo: src, hi: coef bits}
__device__ float     g_sum[OUT_FEAT];
__device__ float     g_sumsq[OUT_FEAT];
__device__ float     g_scale[OUT_FEAT];
__device__ float     g_shift[OUT_FEAT];
__device__ int       g_idx64;                 // 1 if src/dst are int64

__device__ __forceinline__ int get_idx(const void* p, int e, int is64) {
    return is64 ? (int)((const long long*)p)[e] : ((const int*)p)[e];
}

// ----------------------------- init + dtype sniff ---------------------------
__global__ void k_init(const void* __restrict__ src) {
    int i = blockIdx.x * blockDim.x + threadIdx.x;
    if (i < N_NODES) { g_cnt_src[i] = 0; g_cnt_dst[i] = 0; g_cur[i] = 0; }
    if (i < OUT_FEAT) { g_sum[i] = 0.f; g_sumsq[i] = 0.f; }
    if (i == 0) {
        // int64 indices < 2^31 -> zero high words; int32 random data won't
        // produce 256 consecutive zero odd-words.
        const unsigned* p = (const unsigned*)src;
        int is64 = 1;
        for (int k = 0; k < 256; k++)
            if (p[2 * k + 1] != 0u) { is64 = 0; break; }
        g_idx64 = is64;
    }
}

// ----------------------------- degrees on dropped graph ---------------------
__global__ __launch_bounds__(256)
void k_deg(const void* __restrict__ src, const void* __restrict__ dst,
           const float* __restrict__ er) {
    int e = blockIdx.x * blockDim.x + threadIdx.x;
    if (e >= N_EDGES) return;
    if (er[e] >= P_EDGE) {
        int is64 = g_idx64;
        atomicAdd(&g_cnt_src[get_idx(src, e, is64)], 1);
        atomicAdd(&g_cnt_dst[get_idx(dst, e, is64)], 1);
    }
}

// ----------------------------- prefix scan over dst counts ------------------
__global__ __launch_bounds__(1024)
void k_scan() {
    __shared__ int part[1024];
    const int t = threadIdx.x;
    const int CH = (N_NODES + 1023) / 1024;   // 49
    int lo = t * CH, hi = min(lo + CH, N_NODES);
    int s = 0;
    for (int i = lo; i < hi; i++) s += g_cnt_dst[i];
    part[t] = s;
    __syncthreads();
    // inclusive Hillis-Steele scan
    for (int off = 1; off < 1024; off <<= 1) {
        int v = (t >= off) ? part[t - off] : 0;
        __syncthreads();
        part[t] += v;
        __syncthreads();
    }
    int run = part[t] - s;                    // exclusive prefix of this chunk
    for (int i = lo; i < hi; i++) { g_off[i] = run; run += g_cnt_dst[i]; }
    if (t == 1023) g_off[N_NODES] = part[1023];
}

// ----------------------------- scatter edges into dst-sorted CSR ------------
__global__ __launch_bounds__(256)
void k_scatter(const void* __restrict__ src, const void* __restrict__ dst,
               const float* __restrict__ er) {
    int e = blockIdx.x * blockDim.x + threadIdx.x;
    if (e >= N_EDGES) return;
    if (er[e] < P_EDGE) return;
    int is64 = g_idx64;
    int s = get_idx(src, e, is64);
    int d = get_idx(dst, e, is64);
    float cs = fmaxf((float)g_cnt_src[s], 1.f);
    float cd = fmaxf((float)g_cnt_dst[d], 1.f);
    float coef = rsqrtf(cs * cd);
    int pos = g_off[d] + atomicAdd(&g_cur[d], 1);
    long long rec = (long long)(unsigned)s |
                    ((long long)(unsigned)__float_as_int(coef) << 32);
    g_rec[pos] = rec;
}

// ----------------------------- h = features @ W (FFMA2 / f32x2) -------------
// 128x128 tile, BK=16, 256 threads, thread tile 8x8 (row-pairs packed in u64)
#define BM2 128
#define BN2 128
#define BK2 16
__global__ __launch_bounds__(256)
void k_gemm(const float* __restrict__ A, const float* __restrict__ W) {
    __shared__ __align__(16) float As[BK2][BM2 + 4];   // [k][m]
    __shared__ __align__(16) float Bs[BK2][BN2];       // [k][n]

    const int tid  = threadIdx.x;
    const int tx   = tid & 15;        // col group: cols tx*8 .. tx*8+7
    const int ty   = tid >> 4;        // row group: rows ty*8 .. ty*8+7
    const int rowb = blockIdx.x * BM2;

    unsigned long long acc2[4][8];    // [row-pair][col]: lo=row 2rp, hi=row 2rp+1
#pragma unroll
    for (int rp = 0; rp < 4; rp++)
#pragma unroll
        for (int j = 0; j < 8; j++) acc2[rp][j] = 0ull;

    for (int kt = 0; kt < IN_FEAT; kt += BK2) {
        // ---- load A tile (128 x 16), transpose into As[k][m]
        {
            int ar = tid >> 1;                // 0..127
            int kc = (tid & 1) * 8;           // 0 or 8
            int gr = rowb + ar;
            float4 v0, v1;
            if (gr < N_NODES) {
                const float4* ap = (const float4*)(A + (size_t)gr * IN_FEAT + kt + kc);
                v0 = ap[0]; v1 = ap[1];
            } else {
                v0 = make_float4(0.f, 0.f, 0.f, 0.f); v1 = v0;
            }
            As[kc + 0][ar] = v0.x; As[kc + 1][ar] = v0.y;
            As[kc + 2][ar] = v0.z; As[kc + 3][ar] = v0.w;
            As[kc + 4][ar] = v1.x; As[kc + 5][ar] = v1.y;
            As[kc + 6][ar] = v1.z; As[kc + 7][ar] = v1.w;
        }
        // ---- load B tile (16 x 128): 8 floats per thread
        {
            int r = tid >> 4;                 // 0..15
            int c = (tid & 15) * 8;
            const float4* wp = (const float4*)(W + (size_t)(kt + r) * OUT_FEAT + c);
            ((float4*)&Bs[r][c])[0] = wp[0];
            ((float4*)&Bs[r][c])[1] = wp[1];
        }
        __syncthreads();

#pragma unroll
        for (int k = 0; k < BK2; k++) {
            // b columns, duplicated into both f32x2 lanes
            float4 b0 = ((float4*)&Bs[k][tx * 8])[0];
            float4 b1 = ((float4*)&Bs[k][tx * 8])[1];
            unsigned long long bd[8];
            asm("mov.b64 %0,{%1,%1};" : "=l"(bd[0]) : "f"(b0.x));
            asm("mov.b64 %0,{%1,%1};" : "=l"(bd[1]) : "f"(b0.y));
            asm("mov.b64 %0,{%1,%1};" : "=l"(bd[2]) : "f"(b0.z));
            asm("mov.b64 %0,{%1,%1};" : "=l"(bd[3]) : "f"(b0.w));
            asm("mov.b64 %0,{%1,%1};" : "=l"(bd[4]) : "f"(b1.x));
            asm("mov.b64 %0,{%1,%1};" : "=l"(bd[5]) : "f"(b1.y));
            asm("mov.b64 %0,{%1,%1};" : "=l"(bd[6]) : "f"(b1.z));
            asm("mov.b64 %0,{%1,%1};" : "=l"(bd[7]) : "f"(b1.w));
            // a row-pairs directly as 64-bit shared loads
            unsigned long long a2[4];
#pragma unroll
            for (int rp = 0; rp < 4; rp++)
                a2[rp] = *reinterpret_cast<const unsigned long long*>(
                             &As[k][ty * 8 + rp * 2]);
#pragma unroll
            for (int rp = 0; rp < 4; rp++)
#pragma unroll
                for (int j = 0; j < 8; j++)
                    asm("fma.rn.f32x2 %0, %1, %2, %0;"
                        : "+l"(acc2[rp][j]) : "l"(a2[rp]), "l"(bd[j]));
        }
        __syncthreads();
    }

    // ---- epilogue: unpack and store
#pragma unroll
    for (int rp = 0; rp < 4; rp++) {
        float lo[8], hi[8];
#pragma unroll
        for (int j = 0; j < 8; j++)
            asm("mov.b64 {%0,%1}, %2;" : "=f"(lo[j]), "=f"(hi[j]) : "l"(acc2[rp][j]));
        int r0 = rowb + ty * 8 + rp * 2;
        if (r0 < N_NODES) {
            float* p = g_h + (size_t)r0 * OUT_FEAT + tx * 8;
            ((float4*)p)[0] = make_float4(lo[0], lo[1], lo[2], lo[3]);
            ((float4*)p)[1] = make_float4(lo[4], lo[5], lo[6], lo[7]);
        }
        if (r0 + 1 < N_NODES) {
            float* p = g_h + (size_t)(r0 + 1) * OUT_FEAT + tx * 8;
            ((float4*)p)[0] = make_float4(hi[0], hi[1], hi[2], hi[3]);
            ((float4*)p)[1] = make_float4(hi[4], hi[5], hi[6], hi[7]);
        }
    }
}

// ----------------------------- aggregate (warp per node) + fused BN stats ---
__global__ __launch_bounds__(256)
void k_agg(const float* __restrict__ b) {
    const int lane  = threadIdx.x & 31;
    const int wid   = threadIdx.x >> 5;
    const int wg    = (blockIdx.x * blockDim.x + threadIdx.x) >> 5;
    const int nwarp = gridDim.x * (blockDim.x >> 5);

    float4 bb = __ldg(((const float4*)b) + lane);
    float s0 = 0.f, s1 = 0.f, s2 = 0.f, s3 = 0.f;
    float q0 = 0.f, q1 = 0.f, q2 = 0.f, q3 = 0.f;

    for (int node = wg; node < N_NODES; node += nwarp) {
        int beg = g_off[node];
        int end = g_off[node + 1];
        float4 acc = bb;
        for (int j = beg; j < end; j++) {
            long long r = g_rec[j];
            int   s  = (int)(unsigned)r;
            float cf = __int_as_float((int)(r >> 32));
            float4 v = ((const float4*)(g_h + (size_t)s * OUT_FEAT))[lane];
            acc.x = fmaf(cf, v.x, acc.x);
            acc.y = fmaf(cf, v.y, acc.y);
            acc.z = fmaf(cf, v.z, acc.z);
            acc.w = fmaf(cf, v.w, acc.w);
        }
        ((float4*)(g_agg + (size_t)node * OUT_FEAT))[lane] = acc;
        s0 += acc.x; s1 += acc.y; s2 += acc.z; s3 += acc.w;
        q0 += acc.x * acc.x; q1 += acc.y * acc.y;
        q2 += acc.z * acc.z; q3 += acc.w * acc.w;
    }

    // block-level stats reduction
    __shared__ __align__(16) float smS[8][128];
    __shared__ __align__(16) float smQ[8][128];
    ((float4*)&smS[wid][lane * 4])[0] = make_float4(s0, s1, s2, s3);
    ((float4*)&smQ[wid][lane * 4])[0] = make_float4(q0, q1, q2, q3);
    __syncthreads();
    if (threadIdx.x < 128) {
        int c = threadIdx.x;
        float ts = 0.f, tq = 0.f;
#pragma unroll
        for (int w = 0; w < 8; w++) { ts += smS[w][c]; tq += smQ[w][c]; }
        atomicAdd(&g_sum[c], ts);
        atomicAdd(&g_sumsq[c], tq);
    }
}

// ----------------------------- BN params -------------------------------------
__global__ void k_bnparams(const float* __restrict__ gamma,
                           const float* __restrict__ beta) {
    int c = threadIdx.x;
    float inv_n = 1.f / (float)N_NODES;
    float mean = g_sum[c] * inv_n;
    float var  = g_sumsq[c] * inv_n - mean * mean;
    float sc   = rsqrtf(var + BN_EPS) * gamma[c];
    g_scale[c] = sc;
    g_shift[c] = beta[c] - mean * sc;
}

// ----------------------------- finalize: BN + node dropout ------------------
__global__ __launch_bounds__(256)
void k_final(const float* __restrict__ nr, float* __restrict__ out) {
    int i = blockIdx.x * blockDim.x + threadIdx.x;
    const int total4 = N_NODES * OUT_FEAT / 4;
    if (i >= total4) return;
    int c = (i & 31) * 4;
    float4 a = ((const float4*)g_agg)[i];
    float4 r = ((const float4*)nr)[i];
    const float inv_keep = 1.f / (1.f - P_NODE);
    float4 y;
    y.x = (r.x >= P_NODE) ? (a.x * g_scale[c + 0] + g_shift[c + 0]) * inv_keep : 0.f;
    y.y = (r.y >= P_NODE) ? (a.y * g_scale[c + 1] + g_shift[c + 1]) * inv_keep : 0.f;
    y.z = (r.z >= P_NODE) ? (a.z * g_scale[c + 2] + g_shift[c + 2]) * inv_keep : 0.f;
    y.w = (r.w >= P_NODE) ? (a.w * g_scale[c + 3] + g_shift[c + 3]) * inv_keep : 0.f;
    ((float4*)out)[i] = y;
}

// ----------------------------- launch ---------------------------------------
extern "C" void kernel_launch(void* const* d_in, const int* in_sizes, int n_in,
                              void* d_out, int out_size) {
    const float* features = (const float*)d_in[0];
    const float* W        = (const float*)d_in[1];
    const float* b        = (const float*)d_in[2];
    const float* gamma    = (const float*)d_in[3];
    const float* beta     = (const float*)d_in[4];
    const void*  src      = d_in[5];
    const void*  dst      = d_in[6];
    const float* er       = (const float*)d_in[7];
    const float* nr       = (const float*)d_in[8];
    float* out            = (float*)d_out;

    k_init<<<(N_NODES + 255) / 256, 256>>>(src);
    k_gemm<<<(N_NODES + BM2 - 1) / BM2, 256>>>(features, W);
    k_deg<<<(N_EDGES + 255) / 256, 256>>>(src, dst, er);
    k_scan<<<1, 1024>>>();
    k_scatter<<<(N_EDGES + 255) / 256, 256>>>(src, dst, er);
    k_agg<<<1184, 256>>>(b);
    k_bnparams<<<1, OUT_FEAT>>>(gamma, beta);
    const int total4 = N_NODES * OUT_FEAT / 4;
    k_final<<<(total4 + 255) / 256, 256>>>(nr, out);
}

// round 3
// speedup vs baseline: 1.2917x; 1.2031x over previous
#include <cuda_runtime.h>
#include <cstdint>

#define N_NODES  50000
#define N_EDGES  800000
#define IN_FEAT  256
#define OUT_FEAT 128
#define P_EDGE   0.2f
#define P_NODE   0.1f
#define BN_EPS   1e-5f

#define SCAN_CHUNK  256
#define SCAN_BLOCKS ((N_NODES + SCAN_CHUNK - 1) / SCAN_CHUNK)   // 196

// ----------------------------- scratch (no allocs allowed) ------------------
__device__ float     g_h[(size_t)N_NODES * OUT_FEAT];
__device__ float     g_agg[(size_t)N_NODES * OUT_FEAT];
__device__ int       g_cnt_src[N_NODES];
__device__ int       g_cnt_dst[N_NODES];
__device__ int       g_off[N_NODES + 1];
__device__ int       g_cur[N_NODES];
__device__ int       g_part[SCAN_BLOCKS];     // per-block partial sums
__device__ int       g_pbase[SCAN_BLOCKS];    // exclusive base per block
__device__ long long g_rec[N_EDGES];          // packed {lo: src, hi: coef bits}
__device__ float     g_sum[OUT_FEAT];
__device__ float     g_sumsq[OUT_FEAT];
__device__ float     g_scale[OUT_FEAT];
__device__ float     g_shift[OUT_FEAT];
__device__ int       g_idx64;                 // 1 if src/dst are int64

__device__ __forceinline__ int get_idx(const void* p, int e, int is64) {
    return is64 ? (int)((const long long*)p)[e] : ((const int*)p)[e];
}

// ----------------------------- init + dtype sniff ---------------------------
__global__ void k_init(const void* __restrict__ src) {
    int i = blockIdx.x * blockDim.x + threadIdx.x;
    if (i < N_NODES) { g_cnt_src[i] = 0; g_cnt_dst[i] = 0; g_cur[i] = 0; }
    if (i < OUT_FEAT) { g_sum[i] = 0.f; g_sumsq[i] = 0.f; }
    if (i == 0) {
        const unsigned* p = (const unsigned*)src;
        int is64 = 1;
        for (int k = 0; k < 256; k++)
            if (p[2 * k + 1] != 0u) { is64 = 0; break; }
        g_idx64 = is64;
    }
}

// ----------------------------- degrees on dropped graph ---------------------
__global__ __launch_bounds__(256)
void k_deg(const void* __restrict__ src, const void* __restrict__ dst,
           const float* __restrict__ er) {
    int e = blockIdx.x * blockDim.x + threadIdx.x;
    if (e >= N_EDGES) return;
    if (er[e] >= P_EDGE) {
        int is64 = g_idx64;
        atomicAdd(&g_cnt_src[get_idx(src, e, is64)], 1);
        atomicAdd(&g_cnt_dst[get_idx(dst, e, is64)], 1);
    }
}

// ----------------------------- multi-block scan ------------------------------
// stage 1: per-block sums of cnt_dst
__global__ __launch_bounds__(SCAN_CHUNK)
void k_scan1() {
    int i = blockIdx.x * SCAN_CHUNK + threadIdx.x;
    int v = (i < N_NODES) ? g_cnt_dst[i] : 0;
#pragma unroll
    for (int o = 16; o > 0; o >>= 1) v += __shfl_down_sync(~0u, v, o);
    __shared__ int ws[SCAN_CHUNK / 32];
    if ((threadIdx.x & 31) == 0) ws[threadIdx.x >> 5] = v;
    __syncthreads();
    if (threadIdx.x == 0) {
        int s = 0;
#pragma unroll
        for (int w = 0; w < SCAN_CHUNK / 32; w++) s += ws[w];
        g_part[blockIdx.x] = s;
    }
}

// stage 2: scan the 196 partials in one block
__global__ __launch_bounds__(256)
void k_scan2() {
    int t = threadIdx.x;
    int lane = t & 31, w = t >> 5;
    int v = (t < SCAN_BLOCKS) ? g_part[t] : 0;
    int incl = v;
#pragma unroll
    for (int o = 1; o < 32; o <<= 1) {
        int n = __shfl_up_sync(~0u, incl, o);
        if (lane >= o) incl += n;
    }
    __shared__ int ws[8];
    if (lane == 31) ws[w] = incl;
    __syncthreads();
    if (w == 0 && lane < 8) {
        int x = ws[lane];
#pragma unroll
        for (int o = 1; o < 8; o <<= 1) {
            int n = __shfl_up_sync(0xffu, x, o);
            if (lane >= o) x += n;
        }
        ws[lane] = x;
    }
    __syncthreads();
    int base = (w > 0) ? ws[w - 1] : 0;
    if (t < SCAN_BLOCKS) g_pbase[t] = base + incl - v;   // exclusive
    if (t == SCAN_BLOCKS - 1) g_off[N_NODES] = base + incl;
}

// stage 3: per-block exclusive scan + base -> offsets
__global__ __launch_bounds__(SCAN_CHUNK)
void k_scan3() {
    int i = blockIdx.x * SCAN_CHUNK + threadIdx.x;
    int t = threadIdx.x, lane = t & 31, w = t >> 5;
    int v = (i < N_NODES) ? g_cnt_dst[i] : 0;
    int incl = v;
#pragma unroll
    for (int o = 1; o < 32; o <<= 1) {
        int n = __shfl_up_sync(~0u, incl, o);
        if (lane >= o) incl += n;
    }
    __shared__ int ws[SCAN_CHUNK / 32];
    if (lane == 31) ws[w] = incl;
    __syncthreads();
    if (w == 0 && lane < SCAN_CHUNK / 32) {
        int x = ws[lane];
#pragma unroll
        for (int o = 1; o < SCAN_CHUNK / 32; o <<= 1) {
            int n = __shfl_up_sync(0xffu, x, o);
            if (lane >= o) x += n;
        }
        ws[lane] = x;
    }
    __syncthreads();
    int wbase = (w > 0) ? ws[w - 1] : 0;
    if (i < N_NODES)
        g_off[i] = g_pbase[blockIdx.x] + wbase + incl - v;
}

// ----------------------------- scatter edges into dst-sorted CSR ------------
__global__ __launch_bounds__(256)
void k_scatter(const void* __restrict__ src, const void* __restrict__ dst,
               const float* __restrict__ er) {
    int e = blockIdx.x * blockDim.x + threadIdx.x;
    if (e >= N_EDGES) return;
    if (er[e] < P_EDGE) return;
    int is64 = g_idx64;
    int s = get_idx(src, e, is64);
    int d = get_idx(dst, e, is64);
    float cs = fmaxf((float)g_cnt_src[s], 1.f);
    float cd = fmaxf((float)g_cnt_dst[d], 1.f);
    float coef = rsqrtf(cs * cd);
    int pos = g_off[d] + atomicAdd(&g_cur[d], 1);
    long long rec = (long long)(unsigned)s |
                    ((long long)(unsigned)__float_as_int(coef) << 32);
    g_rec[pos] = rec;
}

// ----------------------------- h = features @ W (FFMA2 / f32x2) -------------
#define BM2 128
#define BN2 128
#define BK2 16
__global__ __launch_bounds__(256)
void k_gemm(const float* __restrict__ A, const float* __restrict__ W) {
    __shared__ __align__(16) float As[BK2][BM2 + 4];   // [k][m]
    __shared__ __align__(16) float Bs[BK2][BN2];       // [k][n]

    const int tid  = threadIdx.x;
    const int tx   = tid & 15;
    const int ty   = tid >> 4;
    const int rowb = blockIdx.x * BM2;

    unsigned long long acc2[4][8];
#pragma unroll
    for (int rp = 0; rp < 4; rp++)
#pragma unroll
        for (int j = 0; j < 8; j++) acc2[rp][j] = 0ull;

    for (int kt = 0; kt < IN_FEAT; kt += BK2) {
        {
            int ar = tid >> 1;
            int kc = (tid & 1) * 8;
            int gr = rowb + ar;
            float4 v0, v1;
            if (gr < N_NODES) {
                const float4* ap = (const float4*)(A + (size_t)gr * IN_FEAT + kt + kc);
                v0 = ap[0]; v1 = ap[1];
            } else {
                v0 = make_float4(0.f, 0.f, 0.f, 0.f); v1 = v0;
            }
            As[kc + 0][ar] = v0.x; As[kc + 1][ar] = v0.y;
            As[kc + 2][ar] = v0.z; As[kc + 3][ar] = v0.w;
            As[kc + 4][ar] = v1.x; As[kc + 5][ar] = v1.y;
            As[kc + 6][ar] = v1.z; As[kc + 7][ar] = v1.w;
        }
        {
            int r = tid >> 4;
            int c = (tid & 15) * 8;
            const float4* wp = (const float4*)(W + (size_t)(kt + r) * OUT_FEAT + c);
            ((float4*)&Bs[r][c])[0] = wp[0];
            ((float4*)&Bs[r][c])[1] = wp[1];
        }
        __syncthreads();

#pragma unroll
        for (int k = 0; k < BK2; k++) {
            float4 b0 = ((float4*)&Bs[k][tx * 8])[0];
            float4 b1 = ((float4*)&Bs[k][tx * 8])[1];
            unsigned long long bd[8];
            asm("mov.b64 %0,{%1,%1};" : "=l"(bd[0]) : "f"(b0.x));
            asm("mov.b64 %0,{%1,%1};" : "=l"(bd[1]) : "f"(b0.y));
            asm("mov.b64 %0,{%1,%1};" : "=l"(bd[2]) : "f"(b0.z));
            asm("mov.b64 %0,{%1,%1};" : "=l"(bd[3]) : "f"(b0.w));
            asm("mov.b64 %0,{%1,%1};" : "=l"(bd[4]) : "f"(b1.x));
            asm("mov.b64 %0,{%1,%1};" : "=l"(bd[5]) : "f"(b1.y));
            asm("mov.b64 %0,{%1,%1};" : "=l"(bd[6]) : "f"(b1.z));
            asm("mov.b64 %0,{%1,%1};" : "=l"(bd[7]) : "f"(b1.w));
            unsigned long long a2[4];
#pragma unroll
            for (int rp = 0; rp < 4; rp++)
                a2[rp] = *reinterpret_cast<const unsigned long long*>(
                             &As[k][ty * 8 + rp * 2]);
#pragma unroll
            for (int rp = 0; rp < 4; rp++)
#pragma unroll
                for (int j = 0; j < 8; j++)
                    asm("fma.rn.f32x2 %0, %1, %2, %0;"
                        : "+l"(acc2[rp][j]) : "l"(a2[rp]), "l"(bd[j]));
        }
        __syncthreads();
    }

#pragma unroll
    for (int rp = 0; rp < 4; rp++) {
        float lo[8], hi[8];
#pragma unroll
        for (int j = 0; j < 8; j++)
            asm("mov.b64 {%0,%1}, %2;" : "=f"(lo[j]), "=f"(hi[j]) : "l"(acc2[rp][j]));
        int r0 = rowb + ty * 8 + rp * 2;
        if (r0 < N_NODES) {
            float* p = g_h + (size_t)r0 * OUT_FEAT + tx * 8;
            ((float4*)p)[0] = make_float4(lo[0], lo[1], lo[2], lo[3]);
            ((float4*)p)[1] = make_float4(lo[4], lo[5], lo[6], lo[7]);
        }
        if (r0 + 1 < N_NODES) {
            float* p = g_h + (size_t)(r0 + 1) * OUT_FEAT + tx * 8;
            ((float4*)p)[0] = make_float4(hi[0], hi[1], hi[2], hi[3]);
            ((float4*)p)[1] = make_float4(hi[4], hi[5], hi[6], hi[7]);
        }
    }
}

// ----------------------------- aggregate (warp per node) + fused BN stats ---
__global__ __launch_bounds__(256)
void k_agg(const float* __restrict__ b) {
    const int lane  = threadIdx.x & 31;
    const int wid   = threadIdx.x >> 5;
    const int wg    = (blockIdx.x * blockDim.x + threadIdx.x) >> 5;
    const int nwarp = gridDim.x * (blockDim.x >> 5);

    float4 bb = __ldg(((const float4*)b) + lane);
    float s0 = 0.f, s1 = 0.f, s2 = 0.f, s3 = 0.f;
    float q0 = 0.f, q1 = 0.f, q2 = 0.f, q3 = 0.f;

    for (int node = wg; node < N_NODES; node += nwarp) {
        int beg = g_off[node];
        int end = g_off[node + 1];
        float4 acc = bb;
        for (int j = beg; j < end; j++) {
            long long r = g_rec[j];
            int   s  = (int)(unsigned)r;
            float cf = __int_as_float((int)(r >> 32));
            float4 v = ((const float4*)(g_h + (size_t)s * OUT_FEAT))[lane];
            acc.x = fmaf(cf, v.x, acc.x);
            acc.y = fmaf(cf, v.y, acc.y);
            acc.z = fmaf(cf, v.z, acc.z);
            acc.w = fmaf(cf, v.w, acc.w);
        }
        ((float4*)(g_agg + (size_t)node * OUT_FEAT))[lane] = acc;
        s0 += acc.x; s1 += acc.y; s2 += acc.z; s3 += acc.w;
        q0 += acc.x * acc.x; q1 += acc.y * acc.y;
        q2 += acc.z * acc.z; q3 += acc.w * acc.w;
    }

    __shared__ __align__(16) float smS[8][128];
    __shared__ __align__(16) float smQ[8][128];
    ((float4*)&smS[wid][lane * 4])[0] = make_float4(s0, s1, s2, s3);
    ((float4*)&smQ[wid][lane * 4])[0] = make_float4(q0, q1, q2, q3);
    __syncthreads();
    if (threadIdx.x < 128) {
        int c = threadIdx.x;
        float ts = 0.f, tq = 0.f;
#pragma unroll
        for (int w = 0; w < 8; w++) { ts += smS[w][c]; tq += smQ[w][c]; }
        atomicAdd(&g_sum[c], ts);
        atomicAdd(&g_sumsq[c], tq);
    }
}

// ----------------------------- BN params -------------------------------------
__global__ void k_bnparams(const float* __restrict__ gamma,
                           const float* __restrict__ beta) {
    int c = threadIdx.x;
    float inv_n = 1.f / (float)N_NODES;
    float mean = g_sum[c] * inv_n;
    float var  = g_sumsq[c] * inv_n - mean * mean;
    float sc   = rsqrtf(var + BN_EPS) * gamma[c];
    g_scale[c] = sc;
    g_shift[c] = beta[c] - mean * sc;
}

// ----------------------------- finalize: BN + node dropout ------------------
__global__ __launch_bounds__(256)
void k_final(const float* __restrict__ nr, float* __restrict__ out) {
    int i = blockIdx.x * blockDim.x + threadIdx.x;
    const int total4 = N_NODES * OUT_FEAT / 4;
    if (i >= total4) return;
    int c = (i & 31) * 4;
    float4 a = ((const float4*)g_agg)[i];
    float4 r = ((const float4*)nr)[i];
    const float inv_keep = 1.f / (1.f - P_NODE);
    float4 y;
    y.x = (r.x >= P_NODE) ? (a.x * g_scale[c + 0] + g_shift[c + 0]) * inv_keep : 0.f;
    y.y = (r.y >= P_NODE) ? (a.y * g_scale[c + 1] + g_shift[c + 1]) * inv_keep : 0.f;
    y.z = (r.z >= P_NODE) ? (a.z * g_scale[c + 2] + g_shift[c + 2]) * inv_keep : 0.f;
    y.w = (r.w >= P_NODE) ? (a.w * g_scale[c + 3] + g_shift[c + 3]) * inv_keep : 0.f;
    ((float4*)out)[i] = y;
}

// ----------------------------- launch ---------------------------------------
extern "C" void kernel_launch(void* const* d_in, const int* in_sizes, int n_in,
                              void* d_out, int out_size) {
    const float* features = (const float*)d_in[0];
    const float* W        = (const float*)d_in[1];
    const float* b        = (const float*)d_in[2];
    const float* gamma    = (const float*)d_in[3];
    const float* beta     = (const float*)d_in[4];
    const void*  src      = d_in[5];
    const void*  dst      = d_in[6];
    const float* er       = (const float*)d_in[7];
    const float* nr       = (const float*)d_in[8];
    float* out            = (float*)d_out;

    k_init<<<(N_NODES + 255) / 256, 256>>>(src);
    k_deg<<<(N_EDGES + 255) / 256, 256>>>(src, dst, er);
    k_scan1<<<SCAN_BLOCKS, SCAN_CHUNK>>>();
    k_scan2<<<1, 256>>>();
    k_scan3<<<SCAN_BLOCKS, SCAN_CHUNK>>>();
    k_scatter<<<(N_EDGES + 255) / 256, 256>>>(src, dst, er);
    k_gemm<<<(N_NODES + BM2 - 1) / BM2, 256>>>(features, W);
    k_agg<<<1184, 256>>>(b);
    k_bnparams<<<1, OUT_FEAT>>>(gamma, beta);
    const int total4 = N_NODES * OUT_FEAT / 4;
    k_final<<<(total4 + 255) / 256, 256>>>(nr, out);
}

// round 4
// speedup vs baseline: 1.4610x; 1.1311x over previous
#include <cuda_runtime.h>
#include <cstdint>

#define N_NODES  50000
#define N_EDGES  800000
#define IN_FEAT  256
#define OUT_FEAT 128
#define P_EDGE   0.2f
#define P_NODE   0.1f
#define BN_EPS   1e-5f

#define SCAN_CHUNK  256
#define SCAN_BLOCKS ((N_NODES + SCAN_CHUNK - 1) / SCAN_CHUNK)   // 196

// ----------------------------- scratch (no allocs allowed) ------------------
__device__ float     g_h[(size_t)N_NODES * OUT_FEAT];
__device__ float     g_agg[(size_t)N_NODES * OUT_FEAT];
__device__ int       g_cnt_src[N_NODES];
__device__ int       g_cnt_dst[N_NODES];
__device__ int       g_off[N_NODES + 1];
__device__ int       g_cur[N_NODES];
__device__ int       g_part[SCAN_BLOCKS];
__device__ int       g_pbase[SCAN_BLOCKS];
__device__ long long g_rec[N_EDGES];          // packed {lo: src, hi: coef bits}
__device__ float     g_sum[OUT_FEAT];
__device__ float     g_sumsq[OUT_FEAT];
__device__ int       g_idx64;                 // 1 if src/dst are int64

__device__ __forceinline__ int get_idx(const void* p, int e, int is64) {
    return is64 ? (int)((const long long*)p)[e] : ((const int*)p)[e];
}

// ----------------------------- init + dtype sniff ---------------------------
__global__ void k_init(const void* __restrict__ src) {
    int i = blockIdx.x * blockDim.x + threadIdx.x;
    if (i < N_NODES) { g_cnt_src[i] = 0; g_cnt_dst[i] = 0; g_cur[i] = 0; }
    if (i < OUT_FEAT) { g_sum[i] = 0.f; g_sumsq[i] = 0.f; }
    if (i == 0) {
        const unsigned* p = (const unsigned*)src;
        int is64 = 1;
        for (int k = 0; k < 256; k++)
            if (p[2 * k + 1] != 0u) { is64 = 0; break; }
        g_idx64 = is64;
    }
}

// ----------------------------- degrees on dropped graph ---------------------
__global__ __launch_bounds__(256)
void k_deg(const void* __restrict__ src, const void* __restrict__ dst,
           const float* __restrict__ er) {
    int e = blockIdx.x * blockDim.x + threadIdx.x;
    if (e >= N_EDGES) return;
    if (er[e] >= P_EDGE) {
        int is64 = g_idx64;
        atomicAdd(&g_cnt_src[get_idx(src, e, is64)], 1);
        atomicAdd(&g_cnt_dst[get_idx(dst, e, is64)], 1);
    }
}

// ----------------------------- multi-block scan ------------------------------
__global__ __launch_bounds__(SCAN_CHUNK)
void k_scan1() {
    int i = blockIdx.x * SCAN_CHUNK + threadIdx.x;
    int v = (i < N_NODES) ? g_cnt_dst[i] : 0;
#pragma unroll
    for (int o = 16; o > 0; o >>= 1) v += __shfl_down_sync(~0u, v, o);
    __shared__ int ws[SCAN_CHUNK / 32];
    if ((threadIdx.x & 31) == 0) ws[threadIdx.x >> 5] = v;
    __syncthreads();
    if (threadIdx.x == 0) {
        int s = 0;
#pragma unroll
        for (int w = 0; w < SCAN_CHUNK / 32; w++) s += ws[w];
        g_part[blockIdx.x] = s;
    }
}

__global__ __launch_bounds__(256)
void k_scan2() {
    int t = threadIdx.x;
    int lane = t & 31, w = t >> 5;
    int v = (t < SCAN_BLOCKS) ? g_part[t] : 0;
    int incl = v;
#pragma unroll
    for (int o = 1; o < 32; o <<= 1) {
        int n = __shfl_up_sync(~0u, incl, o);
        if (lane >= o) incl += n;
    }
    __shared__ int ws[8];
    if (lane == 31) ws[w] = incl;
    __syncthreads();
    if (w == 0 && lane < 8) {
        int x = ws[lane];
#pragma unroll
        for (int o = 1; o < 8; o <<= 1) {
            int n = __shfl_up_sync(0xffu, x, o);
            if (lane >= o) x += n;
        }
        ws[lane] = x;
    }
    __syncthreads();
    int base = (w > 0) ? ws[w - 1] : 0;
    if (t < SCAN_BLOCKS) g_pbase[t] = base + incl - v;
    if (t == SCAN_BLOCKS - 1) g_off[N_NODES] = base + incl;
}

__global__ __launch_bounds__(SCAN_CHUNK)
void k_scan3() {
    int i = blockIdx.x * SCAN_CHUNK + threadIdx.x;
    int t = threadIdx.x, lane = t & 31, w = t >> 5;
    int v = (i < N_NODES) ? g_cnt_dst[i] : 0;
    int incl = v;
#pragma unroll
    for (int o = 1; o < 32; o <<= 1) {
        int n = __shfl_up_sync(~0u, incl, o);
        if (lane >= o) incl += n;
    }
    __shared__ int ws[SCAN_CHUNK / 32];
    if (lane == 31) ws[w] = incl;
    __syncthreads();
    if (w == 0 && lane < SCAN_CHUNK / 32) {
        int x = ws[lane];
#pragma unroll
        for (int o = 1; o < SCAN_CHUNK / 32; o <<= 1) {
            int n = __shfl_up_sync(0xffu, x, o);
            if (lane >= o) x += n;
        }
        ws[lane] = x;
    }
    __syncthreads();
    int wbase = (w > 0) ? ws[w - 1] : 0;
    if (i < N_NODES)
        g_off[i] = g_pbase[blockIdx.x] + wbase + incl - v;
}

// ----------------------------- scatter edges into dst-sorted CSR ------------
__global__ __launch_bounds__(256)
void k_scatter(const void* __restrict__ src, const void* __restrict__ dst,
               const float* __restrict__ er) {
    int e = blockIdx.x * blockDim.x + threadIdx.x;
    if (e >= N_EDGES) return;
    if (er[e] < P_EDGE) return;
    int is64 = g_idx64;
    int s = get_idx(src, e, is64);
    int d = get_idx(dst, e, is64);
    float cs = fmaxf((float)g_cnt_src[s], 1.f);
    float cd = fmaxf((float)g_cnt_dst[d], 1.f);
    float coef = rsqrtf(cs * cd);
    int pos = g_off[d] + atomicAdd(&g_cur[d], 1);
    long long rec = (long long)(unsigned)s |
                    ((long long)(unsigned)__float_as_int(coef) << 32);
    g_rec[pos] = rec;
}

// ----------------------------- h = features @ W (FFMA2 / f32x2) -------------
#define BM2 128
#define BN2 128
#define BK2 16
__global__ __launch_bounds__(256)
void k_gemm(const float* __restrict__ A, const float* __restrict__ W) {
    __shared__ __align__(16) float As[BK2][BM2 + 4];
    __shared__ __align__(16) float Bs[BK2][BN2];

    const int tid  = threadIdx.x;
    const int tx   = tid & 15;
    const int ty   = tid >> 4;
    const int rowb = blockIdx.x * BM2;

    unsigned long long acc2[4][8];
#pragma unroll
    for (int rp = 0; rp < 4; rp++)
#pragma unroll
        for (int j = 0; j < 8; j++) acc2[rp][j] = 0ull;

    for (int kt = 0; kt < IN_FEAT; kt += BK2) {
        {
            int ar = tid >> 1;
            int kc = (tid & 1) * 8;
            int gr = rowb + ar;
            float4 v0, v1;
            if (gr < N_NODES) {
                const float4* ap = (const float4*)(A + (size_t)gr * IN_FEAT + kt + kc);
                v0 = ap[0]; v1 = ap[1];
            } else {
                v0 = make_float4(0.f, 0.f, 0.f, 0.f); v1 = v0;
            }
            As[kc + 0][ar] = v0.x; As[kc + 1][ar] = v0.y;
            As[kc + 2][ar] = v0.z; As[kc + 3][ar] = v0.w;
            As[kc + 4][ar] = v1.x; As[kc + 5][ar] = v1.y;
            As[kc + 6][ar] = v1.z; As[kc + 7][ar] = v1.w;
        }
        {
            int r = tid >> 4;
            int c = (tid & 15) * 8;
            const float4* wp = (const float4*)(W + (size_t)(kt + r) * OUT_FEAT + c);
            ((float4*)&Bs[r][c])[0] = wp[0];
            ((float4*)&Bs[r][c])[1] = wp[1];
        }
        __syncthreads();

#pragma unroll
        for (int k = 0; k < BK2; k++) {
            float4 b0 = ((float4*)&Bs[k][tx * 8])[0];
            float4 b1 = ((float4*)&Bs[k][tx * 8])[1];
            unsigned long long bd[8];
            asm("mov.b64 %0,{%1,%1};" : "=l"(bd[0]) : "f"(b0.x));
            asm("mov.b64 %0,{%1,%1};" : "=l"(bd[1]) : "f"(b0.y));
            asm("mov.b64 %0,{%1,%1};" : "=l"(bd[2]) : "f"(b0.z));
            asm("mov.b64 %0,{%1,%1};" : "=l"(bd[3]) : "f"(b0.w));
            asm("mov.b64 %0,{%1,%1};" : "=l"(bd[4]) : "f"(b1.x));
            asm("mov.b64 %0,{%1,%1};" : "=l"(bd[5]) : "f"(b1.y));
            asm("mov.b64 %0,{%1,%1};" : "=l"(bd[6]) : "f"(b1.z));
            asm("mov.b64 %0,{%1,%1};" : "=l"(bd[7]) : "f"(b1.w));
            unsigned long long a2[4];
#pragma unroll
            for (int rp = 0; rp < 4; rp++)
                a2[rp] = *reinterpret_cast<const unsigned long long*>(
                             &As[k][ty * 8 + rp * 2]);
#pragma unroll
            for (int rp = 0; rp < 4; rp++)
#pragma unroll
                for (int j = 0; j < 8; j++)
                    asm("fma.rn.f32x2 %0, %1, %2, %0;"
                        : "+l"(acc2[rp][j]) : "l"(a2[rp]), "l"(bd[j]));
        }
        __syncthreads();
    }

#pragma unroll
    for (int rp = 0; rp < 4; rp++) {
        float lo[8], hi[8];
#pragma unroll
        for (int j = 0; j < 8; j++)
            asm("mov.b64 {%0,%1}, %2;" : "=f"(lo[j]), "=f"(hi[j]) : "l"(acc2[rp][j]));
        int r0 = rowb + ty * 8 + rp * 2;
        if (r0 < N_NODES) {
            float* p = g_h + (size_t)r0 * OUT_FEAT + tx * 8;
            ((float4*)p)[0] = make_float4(lo[0], lo[1], lo[2], lo[3]);
            ((float4*)p)[1] = make_float4(lo[4], lo[5], lo[6], lo[7]);
        }
        if (r0 + 1 < N_NODES) {
            float* p = g_h + (size_t)(r0 + 1) * OUT_FEAT + tx * 8;
            ((float4*)p)[0] = make_float4(hi[0], hi[1], hi[2], hi[3]);
            ((float4*)p)[1] = make_float4(hi[4], hi[5], hi[6], hi[7]);
        }
    }
}

// ----------------------------- aggregate (warp per node) + fused BN stats ---
__global__ __launch_bounds__(256)
void k_agg(const float* __restrict__ b) {
    const int lane  = threadIdx.x & 31;
    const int wid   = threadIdx.x >> 5;
    const int wg    = (blockIdx.x * blockDim.x + threadIdx.x) >> 5;
    const int nwarp = gridDim.x * (blockDim.x >> 5);

    float4 bb = __ldg(((const float4*)b) + lane);
    float s0 = 0.f, s1 = 0.f, s2 = 0.f, s3 = 0.f;
    float q0 = 0.f, q1 = 0.f, q2 = 0.f, q3 = 0.f;

    for (int node = wg; node < N_NODES; node += nwarp) {
        int beg = g_off[node];
        int end = g_off[node + 1];
        float4 acc = bb;
        for (int j = beg; j < end; j++) {
            long long r = g_rec[j];
            int   s  = (int)(unsigned)r;
            float cf = __int_as_float((int)(r >> 32));
            float4 v = ((const float4*)(g_h + (size_t)s * OUT_FEAT))[lane];
            acc.x = fmaf(cf, v.x, acc.x);
            acc.y = fmaf(cf, v.y, acc.y);
            acc.z = fmaf(cf, v.z, acc.z);
            acc.w = fmaf(cf, v.w, acc.w);
        }
        ((float4*)(g_agg + (size_t)node * OUT_FEAT))[lane] = acc;
        s0 += acc.x; s1 += acc.y; s2 += acc.z; s3 += acc.w;
        q0 += acc.x * acc.x; q1 += acc.y * acc.y;
        q2 += acc.z * acc.z; q3 += acc.w * acc.w;
    }

    __shared__ __align__(16) float smS[8][128];
    __shared__ __align__(16) float smQ[8][128];
    ((float4*)&smS[wid][lane * 4])[0] = make_float4(s0, s1, s2, s3);
    ((float4*)&smQ[wid][lane * 4])[0] = make_float4(q0, q1, q2, q3);
    __syncthreads();
    if (threadIdx.x < 128) {
        int c = threadIdx.x;
        float ts = 0.f, tq = 0.f;
#pragma unroll
        for (int w = 0; w < 8; w++) { ts += smS[w][c]; tq += smQ[w][c]; }
        atomicAdd(&g_sum[c], ts);
        atomicAdd(&g_sumsq[c], tq);
    }
}

// ----------------------------- finalize: BN params + BN + node dropout ------
__global__ __launch_bounds__(256)
void k_final(const float* __restrict__ nr, const float* __restrict__ gamma,
             const float* __restrict__ beta, float* __restrict__ out) {
    __shared__ float s_scale[OUT_FEAT];
    __shared__ float s_shift[OUT_FEAT];
    if (threadIdx.x < OUT_FEAT) {
        int c = threadIdx.x;
        const float inv_n = 1.f / (float)N_NODES;
        float mean = g_sum[c] * inv_n;
        float var  = g_sumsq[c] * inv_n - mean * mean;
        float sc   = rsqrtf(var + BN_EPS) * gamma[c];
        s_scale[c] = sc;
        s_shift[c] = beta[c] - mean * sc;
    }
    __syncthreads();

    int i = blockIdx.x * blockDim.x + threadIdx.x;
    const int total4 = N_NODES * OUT_FEAT / 4;
    if (i >= total4) return;
    int c = (i & 31) * 4;
    float4 a = ((const float4*)g_agg)[i];
    float4 r = ((const float4*)nr)[i];
    const float inv_keep = 1.f / (1.f - P_NODE);
    float4 y;
    y.x = (r.x >= P_NODE) ? (a.x * s_scale[c + 0] + s_shift[c + 0]) * inv_keep : 0.f;
    y.y = (r.y >= P_NODE) ? (a.y * s_scale[c + 1] + s_shift[c + 1]) * inv_keep : 0.f;
    y.z = (r.z >= P_NODE) ? (a.z * s_scale[c + 2] + s_shift[c + 2]) * inv_keep : 0.f;
    y.w = (r.w >= P_NODE) ? (a.w * s_scale[c + 3] + s_shift[c + 3]) * inv_keep : 0.f;
    ((float4*)out)[i] = y;
}

// ----------------------------- launch ---------------------------------------
extern "C" void kernel_launch(void* const* d_in, const int* in_sizes, int n_in,
                              void* d_out, int out_size) {
    const float* features = (const float*)d_in[0];
    const float* W        = (const float*)d_in[1];
    const float* b        = (const float*)d_in[2];
    const float* gamma    = (const float*)d_in[3];
    const float* beta     = (const float*)d_in[4];
    const void*  src      = d_in[5];
    const void*  dst      = d_in[6];
    const float* er       = (const float*)d_in[7];
    const float* nr       = (const float*)d_in[8];
    float* out            = (float*)d_out;

    // lazily-created side stream + fork/join events (resources, not work;
    // identical launch sequence every call)
    static cudaStream_t s_side = nullptr;
    static cudaEvent_t  s_fork = nullptr, s_join = nullptr;
    if (s_side == nullptr) {
        cudaStreamCreateWithFlags(&s_side, cudaStreamNonBlocking);
        cudaEventCreateWithFlags(&s_fork, cudaEventDisableTiming);
        cudaEventCreateWithFlags(&s_join, cudaEventDisableTiming);
    }

    // fork: GEMM branch (depends only on features/W)
    cudaEventRecord(s_fork, 0);
    cudaStreamWaitEvent(s_side, s_fork, 0);
    k_gemm<<<(N_NODES + BM2 - 1) / BM2, 256, 0, s_side>>>(features, W);
    cudaEventRecord(s_join, s_side);

    // main branch: edge chain
    k_init<<<(N_NODES + 255) / 256, 256>>>(src);
    k_deg<<<(N_EDGES + 255) / 256, 256>>>(src, dst, er);
    k_scan1<<<SCAN_BLOCKS, SCAN_CHUNK>>>();
    k_scan2<<<1, 256>>>();
    k_scan3<<<SCAN_BLOCKS, SCAN_CHUNK>>>();
    k_scatter<<<(N_EDGES + 255) / 256, 256>>>(src, dst, er);

    // join: aggregation needs both g_h and the CSR
    cudaStreamWaitEvent(0, s_join, 0);
    k_agg<<<1184, 256>>>(b);
    const int total4 = N_NODES * OUT_FEAT / 4;
    k_final<<<(total4 + 255) / 256, 256>>>(nr, gamma, beta, out);
}